// round 8
// baseline (speedup 1.0000x reference)
#include <cuda_runtime.h>
#include <cuda_bf16.h>
#include <mma.h>

using namespace nvcuda;

// ---------------------------------------------------------------------------
// Dims (fixed by problem): DIN=256, H=8, D=32 (H*D=256), DG=512.
// GEMM per GAT: [N,256] @ [256,256], fused with online-softmax GAT reduction.
// ---------------------------------------------------------------------------

#define WLD 264   // bf16 leading dim for W and A tiles (mult of 8)
#define CLD 260   // fp32 leading dim for C tile (mult of 4)

struct GatSmem {
  __nv_bfloat16 W[256 * WLD];   // 135168 B : full Wl, bf16
  float U[64 * CLD];            //  66560 B : A tile (bf16, aliased) then C tile (fp32)
  float att[256];               // per-head attention vectors [8][32]
  float xrb[256];               // bl + xr (target-node message + bias)
  float wsm[64 * 8];            // per-row,per-head logits -> exp weights
  float acc[256];               // online alpha-weighted sum of xl
  float mrun[8];
  float srun[8];
  float scale[8];
};
// total ~206944 B < 227KB max dynamic smem

__device__ float d_xrb_v[256];
__device__ float d_xrb_s[256];
__device__ float d_pm[2][256][8];
__device__ float d_ps[2][256][8];
__device__ float d_pacc[2][256][256];

// block reduce over 512 threads (16 warps)
__device__ __forceinline__ float blk_reduce_sum_512(float v, float* red) {
  int t = threadIdx.x;
#pragma unroll
  for (int o = 16; o; o >>= 1) v += __shfl_xor_sync(0xffffffffu, v, o);
  if ((t & 31) == 0) red[t >> 5] = v;
  __syncthreads();
  if (t < 32) {
    float s = (t < 16) ? red[t] : 0.f;
#pragma unroll
    for (int o = 8; o; o >>= 1) s += __shfl_xor_sync(0xffffffffu, s, o);
    if (t == 0) red[0] = s;
  }
  __syncthreads();
  float r = red[0];
  __syncthreads();
  return r;
}

// ---------------------------------------------------------------------------
// Prep: xt_v = relu(LN(prev)) @ g2v_W + g2v_b ; xt_s likewise.
// Then xrb_v = v_bl + v_br + xt_v @ v_Wr ; xrb_s likewise. One block, 512 thr.
// ---------------------------------------------------------------------------
__global__ void prep_kernel(const float* __restrict__ prev,
    const float* __restrict__ g2v_ln_s, const float* __restrict__ g2v_ln_b,
    const float* __restrict__ g2v_W, const float* __restrict__ g2v_b,
    const float* __restrict__ g2s_ln_s, const float* __restrict__ g2s_ln_b,
    const float* __restrict__ g2s_W, const float* __restrict__ g2s_b,
    const float* __restrict__ v_Wr, const float* __restrict__ v_br, const float* __restrict__ v_bl,
    const float* __restrict__ s_Wr, const float* __restrict__ s_br, const float* __restrict__ s_bl)
{
  __shared__ float yv[512], ys[512], xt[512], red[16];
  int t = threadIdx.x;
  float x = prev[t];
  float mean = blk_reduce_sum_512(x, red) * (1.f / 512.f);
  float dv = x - mean;
  float var = blk_reduce_sum_512(dv * dv, red) * (1.f / 512.f);
  float rstd = rsqrtf(var + 1e-5f);
  yv[t] = fmaxf(dv * rstd * g2v_ln_s[t] + g2v_ln_b[t], 0.f);
  ys[t] = fmaxf(dv * rstd * g2s_ln_s[t] + g2s_ln_b[t], 0.f);
  __syncthreads();
  {
    const float* W = (t < 256) ? g2v_W : g2s_W;
    const float* y = (t < 256) ? yv : ys;
    int c = t & 255;
    float acc = (t < 256) ? g2v_b[c] : g2s_b[c];
#pragma unroll 4
    for (int k = 0; k < 512; k++) acc = fmaf(y[k], W[k * 256 + c], acc);
    xt[t] = acc;
  }
  __syncthreads();
  {
    const float* W = (t < 256) ? v_Wr : s_Wr;
    const float* xv = (t < 256) ? xt : (xt + 256);
    int c = t & 255;
    float acc = (t < 256) ? (v_br[c] + v_bl[c]) : (s_br[c] + s_bl[c]);
#pragma unroll 4
    for (int k = 0; k < 256; k++) acc = fmaf(xv[k], W[k * 256 + c], acc);
    if (t < 256) d_xrb_v[c] = acc; else d_xrb_s[c] = acc;
  }
}

// ---------------------------------------------------------------------------
// Fused GEMM + GATv2 online-softmax reduction. Persistent blocks, W in smem.
// Each block: subtiles of 64 rows, C = A@W (bf16 wmma), logits, online acc.
// ---------------------------------------------------------------------------
__global__ __launch_bounds__(256, 1)
void gat_kernel(const float* __restrict__ X, int nrows, int nsub,
                const float* __restrict__ Wl, const float* __restrict__ attw,
                int slot)
{
  extern __shared__ char smem_raw[];
  GatSmem& s = *reinterpret_cast<GatSmem*>(smem_raw);
  const int tid = threadIdx.x;
  const int warp = tid >> 5;

  // load full Wl -> bf16 smem (256x256, coalesced float4)
  {
    const float4* W4 = reinterpret_cast<const float4*>(Wl);
#pragma unroll 4
    for (int i = tid; i < 16384; i += 256) {
      float4 v = W4[i];
      int k = i >> 6, n = (i & 63) << 2;
      __nv_bfloat162* q = reinterpret_cast<__nv_bfloat162*>(&s.W[k * WLD + n]);
      q[0] = __floats2bfloat162_rn(v.x, v.y);
      q[1] = __floats2bfloat162_rn(v.z, v.w);
    }
  }
  s.att[tid] = attw[tid];
  s.xrb[tid] = slot ? d_xrb_s[tid] : d_xrb_v[tid];
  s.acc[tid] = 0.f;
  if (tid < 8) { s.mrun[tid] = -INFINITY; s.srun[tid] = 0.f; }
  __syncthreads();

  __nv_bfloat16* A = reinterpret_cast<__nv_bfloat16*>(s.U);
  const int wr0 = (warp >> 1) << 4;   // warp row strip: 0/16/32/48
  const int wc0 = (warp & 1) << 7;    // warp col half: 0/128

  for (int sub = blockIdx.x; sub < nsub; sub += gridDim.x) {
    const int row0 = sub * 64;
    const float4* X4 = reinterpret_cast<const float4*>(X + (size_t)row0 * 256);
    // ---- load A tile (64x256 fp32 -> bf16 smem) ----
#pragma unroll
    for (int i = tid; i < 4096; i += 256) {
      int r = i >> 6, k = (i & 63) << 2;
      __nv_bfloat162* q = reinterpret_cast<__nv_bfloat162*>(&A[r * WLD + k]);
      if (row0 + r < nrows) {
        float4 v = X4[i];
        q[0] = __floats2bfloat162_rn(v.x, v.y);
        q[1] = __floats2bfloat162_rn(v.z, v.w);
      } else {
        q[0] = __floats2bfloat162_rn(0.f, 0.f);
        q[1] = __floats2bfloat162_rn(0.f, 0.f);
      }
    }
    __syncthreads();

    // ---- mainloop: C[64,256] = A @ W, per-warp 16x128 strip ----
    wmma::fragment<wmma::accumulator, 16, 16, 16, float> c[8];
#pragma unroll
    for (int j = 0; j < 8; j++) wmma::fill_fragment(c[j], 0.f);
#pragma unroll
    for (int kt = 0; kt < 16; kt++) {
      wmma::fragment<wmma::matrix_a, 16, 16, 16, __nv_bfloat16, wmma::row_major> a;
      wmma::load_matrix_sync(a, &A[wr0 * WLD + (kt << 4)], WLD);
#pragma unroll
      for (int j = 0; j < 8; j++) {
        wmma::fragment<wmma::matrix_b, 16, 16, 16, __nv_bfloat16, wmma::row_major> b;
        wmma::load_matrix_sync(b, &s.W[(kt << 4) * WLD + wc0 + (j << 4)], WLD);
        wmma::mma_sync(c[j], a, b, c[j]);
      }
    }
    __syncthreads();   // all warps done reading A; reuse U as fp32 C
#pragma unroll
    for (int j = 0; j < 8; j++)
      wmma::store_matrix_sync(&s.U[wr0 * CLD + wc0 + (j << 4)], c[j], CLD,
                              wmma::mem_row_major);
    __syncthreads();

    // ---- logits: l[r][h] = att_h . lrelu(C[r,h*32:..] + xrb) ----
#pragma unroll
    for (int half = 0; half < 2; half++) {
      int p = tid + (half << 8);
      int h = p >> 6, r = p & 63;
      const float* Crow = &s.U[r * CLD + (h << 5)];
      const float* ath = &s.att[h << 5];
      const float* xr = &s.xrb[h << 5];
      float l;
      if (row0 + r < nrows) {
        l = 0.f;
#pragma unroll
        for (int d = 0; d < 32; d++) {
          float z = Crow[d] + xr[d];
          z = (z > 0.f) ? z : 0.2f * z;
          l = fmaf(ath[d], z, l);
        }
      } else {
        l = -INFINITY;
      }
      s.wsm[r * 8 + h] = l;
    }
    __syncthreads();
    // per-head running max + rescale factor
    if (tid < 8) {
      float msub = -INFINITY;
      for (int r = 0; r < 64; r++) msub = fmaxf(msub, s.wsm[r * 8 + tid]);
      float mold = s.mrun[tid];
      float mn = fmaxf(mold, msub);
      s.scale[tid] = __expf(mold - mn);   // 0 on first tile (mold=-inf)
      s.mrun[tid] = mn;
    }
    __syncthreads();
#pragma unroll
    for (int half = 0; half < 2; half++) {
      int p = tid + (half << 8);
      int h = p >> 6, r = p & 63;
      s.wsm[r * 8 + h] = __expf(s.wsm[r * 8 + h] - s.mrun[h]);  // exp(-inf)=0
    }
    __syncthreads();
    // acc[c] = acc[c]*scale + sum_r w[r,h(c)] * C[r,c]
    {
      int h = tid >> 5;
      float a = s.acc[tid] * s.scale[h];
#pragma unroll 4
      for (int r = 0; r < 64; r++)
        a = fmaf(s.wsm[r * 8 + h], s.U[r * CLD + tid], a);
      s.acc[tid] = a;
    }
    if (tid < 8) {
      float ss = 0.f;
      for (int r = 0; r < 64; r++) ss += s.wsm[r * 8 + tid];
      s.srun[tid] = s.srun[tid] * s.scale[tid] + ss;
    }
    __syncthreads();
  }

  // ---- write block partials ----
  if (tid < 8) {
    d_pm[slot][blockIdx.x][tid] = s.mrun[tid];
    d_ps[slot][blockIdx.x][tid] = s.srun[tid];
  }
  d_pacc[slot][blockIdx.x][tid] = s.acc[tid];
}

// ---------------------------------------------------------------------------
// Finalize: combine block partials -> v2g/s2g, residual, LN, relu, MLP, skip.
// One block, 512 threads.
// ---------------------------------------------------------------------------
__global__ void finalize_kernel(const float* __restrict__ prev,
    const float* __restrict__ v_bl, const float* __restrict__ v_bias,
    const float* __restrict__ s_bl, const float* __restrict__ s_bias,
    const float* __restrict__ pre_ln_s, const float* __restrict__ pre_ln_b,
    const float* __restrict__ mlp_W, const float* __restrict__ mlp_b,
    int Gv, int Gs, float* __restrict__ out)
{
  __shared__ float x[512], y[512], Mh[16], Sh[16], red[16];
  int t = threadIdx.x;
  if (t < 16) {
    int sl = t >> 3, h = t & 7;
    int G = sl ? Gs : Gv;
    float M = -INFINITY;
    for (int b = 0; b < G; b++) M = fmaxf(M, d_pm[sl][b][h]);
    float S = 0.f;
    for (int b = 0; b < G; b++) S += d_ps[sl][b][h] * __expf(d_pm[sl][b][h] - M);
    Mh[t] = M; Sh[t] = S;
  }
  __syncthreads();
  {
    int sl = t >> 8, c = t & 255, h = c >> 5;
    int G = sl ? Gs : Gv;
    float M = Mh[sl * 8 + h];
    float F = 0.f;
    for (int b = 0; b < G; b++)
      F = fmaf(d_pacc[sl][b][c], __expf(d_pm[sl][b][h] - M), F);
    float g = F / Sh[sl * 8 + h] +
              (sl ? (s_bl[c] + s_bias[c]) : (v_bl[c] + v_bias[c]));
    x[t] = prev[t] + g;
  }
  __syncthreads();
  float xv = x[t];
  float mean = blk_reduce_sum_512(xv, red) * (1.f / 512.f);
  float dv = xv - mean;
  float var = blk_reduce_sum_512(dv * dv, red) * (1.f / 512.f);
  float rstd = rsqrtf(var + 1e-5f);
  y[t] = fmaxf(dv * rstd * pre_ln_s[t] + pre_ln_b[t], 0.f);
  __syncthreads();
  float acc = mlp_b[t];
#pragma unroll 4
  for (int k = 0; k < 512; k++) acc = fmaf(y[k], mlp_W[k * 512 + t], acc);
  out[t] = xv + acc;
}

// ---------------------------------------------------------------------------
extern "C" void kernel_launch(void* const* d_in, const int* in_sizes, int n_in,
                              void* d_out, int out_size) {
  const float* view     = (const float*)d_in[0];
  const float* scene    = (const float*)d_in[1];
  const float* prev     = (const float*)d_in[2];
  const float* g2v_ln_s = (const float*)d_in[3];
  const float* g2v_ln_b = (const float*)d_in[4];
  const float* g2v_W    = (const float*)d_in[5];
  const float* g2v_b    = (const float*)d_in[6];
  const float* g2s_ln_s = (const float*)d_in[7];
  const float* g2s_ln_b = (const float*)d_in[8];
  const float* g2s_W    = (const float*)d_in[9];
  const float* g2s_b    = (const float*)d_in[10];
  const float* v_Wl     = (const float*)d_in[11];
  const float* v_bl     = (const float*)d_in[12];
  const float* v_Wr     = (const float*)d_in[13];
  const float* v_br     = (const float*)d_in[14];
  const float* v_att    = (const float*)d_in[15];
  const float* v_bias   = (const float*)d_in[16];
  const float* s_Wl     = (const float*)d_in[17];
  const float* s_bl     = (const float*)d_in[18];
  const float* s_Wr     = (const float*)d_in[19];
  const float* s_br     = (const float*)d_in[20];
  const float* s_att    = (const float*)d_in[21];
  const float* s_bias   = (const float*)d_in[22];
  const float* pre_ln_s = (const float*)d_in[23];
  const float* pre_ln_b = (const float*)d_in[24];
  const float* mlp_W    = (const float*)d_in[25];
  const float* mlp_b    = (const float*)d_in[26];
  float* out = (float*)d_out;

  int smem = (int)sizeof(GatSmem);
  cudaFuncSetAttribute(gat_kernel, cudaFuncAttributeMaxDynamicSharedMemorySize, smem);

  prep_kernel<<<1, 512>>>(prev, g2v_ln_s, g2v_ln_b, g2v_W, g2v_b,
                          g2s_ln_s, g2s_ln_b, g2s_W, g2s_b,
                          v_Wr, v_br, v_bl, s_Wr, s_br, s_bl);

  int nv = in_sizes[0] / 256;
  int ns = in_sizes[1] / 256;
  int nsub_v = (nv + 63) / 64;
  int nsub_s = (ns + 63) / 64;
  int Gv = nsub_v < 64 ? nsub_v : 64;
  int Gs = nsub_s < 148 ? nsub_s : 148;

  gat_kernel<<<Gv, 256, smem>>>(view, nv, nsub_v, v_Wl, v_att, 0);
  gat_kernel<<<Gs, 256, smem>>>(scene, ns, nsub_s, s_Wl, s_att, 1);

  finalize_kernel<<<1, 512>>>(prev, v_bl, v_bias, s_bl, s_bias,
                              pre_ln_s, pre_ln_b, mlp_W, mlp_b, Gv, Gs, out);
}

// round 9
// speedup vs baseline: 1.5880x; 1.5880x over previous
#include <cuda_runtime.h>
#include <cuda_bf16.h>
#include <mma.h>

using namespace nvcuda;

// Dims fixed by problem: DIN=256, H=8, D=32 (H*D=256), DG=512.
// Both GATs: [N,256] @ [256,256] fused with online-softmax star-GAT reduction.

#define WLD 264   // bf16 leading dim for W (16B-aligned rows, conflict-padded)
#define ALD 264   // bf16 leading dim for A tile
#define CLD 260   // fp32 leading dim for C tile

struct GatSmem {
  __nv_bfloat16 W[256 * WLD];   // 135168 B : full Wl, bf16
  float U[64 * CLD];            //  66560 B : A tile (bf16, aliased) then C (fp32)
  float att[256];
  float xrb[256];               // bl + br + xt@Wr
  float wsm[64 * 8];            // logits -> exp weights, flat [r*8+h]
  float acc[256];
  float mrun[8], srun[8], scale[8];
};
// ~206.9 KB

__device__ float d_xrb_v[256];
__device__ float d_xrb_s[256];
__device__ float d_pm[2][256][8];
__device__ float d_ps[2][256][8];
__device__ float d_pacc[2][256][256];
__device__ float d_x[512];
__device__ float d_y[512];

__device__ __forceinline__ float blk_reduce_sum_512(float v, float* red) {
  int t = threadIdx.x;
#pragma unroll
  for (int o = 16; o; o >>= 1) v += __shfl_xor_sync(0xffffffffu, v, o);
  if ((t & 31) == 0) red[t >> 5] = v;
  __syncthreads();
  if (t < 32) {
    float s = (t < 16) ? red[t] : 0.f;
#pragma unroll
    for (int o = 8; o; o >>= 1) s += __shfl_xor_sync(0xffffffffu, s, o);
    if (t == 0) red[0] = s;
  }
  __syncthreads();
  float r = red[0];
  __syncthreads();
  return r;
}

// ---------------------------------------------------------------------------
// Prep: xt = relu(LN(prev)) @ gW + gb ;  xrb = bl + br + xt @ Wr  (both slots)
// ---------------------------------------------------------------------------
__global__ void prep_kernel(const float* __restrict__ prev,
    const float* __restrict__ g2v_ln_s, const float* __restrict__ g2v_ln_b,
    const float* __restrict__ g2v_W, const float* __restrict__ g2v_b,
    const float* __restrict__ g2s_ln_s, const float* __restrict__ g2s_ln_b,
    const float* __restrict__ g2s_W, const float* __restrict__ g2s_b,
    const float* __restrict__ v_Wr, const float* __restrict__ v_br, const float* __restrict__ v_bl,
    const float* __restrict__ s_Wr, const float* __restrict__ s_br, const float* __restrict__ s_bl)
{
  __shared__ float yv[512], ys[512], xt[512], red[16];
  int t = threadIdx.x;
  float x = prev[t];
  float mean = blk_reduce_sum_512(x, red) * (1.f / 512.f);
  float dv = x - mean;
  float var = blk_reduce_sum_512(dv * dv, red) * (1.f / 512.f);
  float rstd = rsqrtf(var + 1e-5f);
  yv[t] = fmaxf(dv * rstd * g2v_ln_s[t] + g2v_ln_b[t], 0.f);
  ys[t] = fmaxf(dv * rstd * g2s_ln_s[t] + g2s_ln_b[t], 0.f);
  __syncthreads();
  {
    const float* W = (t < 256) ? g2v_W : g2s_W;
    const float* y = (t < 256) ? yv : ys;
    int c = t & 255;
    float a0 = (t < 256) ? g2v_b[c] : g2s_b[c];
    float a1 = 0.f, a2 = 0.f, a3 = 0.f;
#pragma unroll 4
    for (int k = 0; k < 512; k += 4) {
      a0 = fmaf(y[k + 0], W[(k + 0) * 256 + c], a0);
      a1 = fmaf(y[k + 1], W[(k + 1) * 256 + c], a1);
      a2 = fmaf(y[k + 2], W[(k + 2) * 256 + c], a2);
      a3 = fmaf(y[k + 3], W[(k + 3) * 256 + c], a3);
    }
    xt[t] = (a0 + a1) + (a2 + a3);
  }
  __syncthreads();
  {
    const float* W = (t < 256) ? v_Wr : s_Wr;
    const float* xv = (t < 256) ? xt : (xt + 256);
    int c = t & 255;
    float a0 = (t < 256) ? (v_br[c] + v_bl[c]) : (s_br[c] + s_bl[c]);
    float a1 = 0.f, a2 = 0.f, a3 = 0.f;
#pragma unroll 4
    for (int k = 0; k < 256; k += 4) {
      a0 = fmaf(xv[k + 0], W[(k + 0) * 256 + c], a0);
      a1 = fmaf(xv[k + 1], W[(k + 1) * 256 + c], a1);
      a2 = fmaf(xv[k + 2], W[(k + 2) * 256 + c], a2);
      a3 = fmaf(xv[k + 3], W[(k + 3) * 256 + c], a3);
    }
    float r = (a0 + a1) + (a2 + a3);
    if (t < 256) d_xrb_v[c] = r; else d_xrb_s[c] = r;
  }
}

// ---------------------------------------------------------------------------
// Fused GEMM + GATv2 online softmax. Persistent blocks; scene blocks [0,Bs),
// view blocks [Bs,Bs+Bv). Register-prefetched A tiles, 32x64 warp MMA tiles.
// ---------------------------------------------------------------------------
__global__ __launch_bounds__(256, 1)
void gat_kernel(const float* __restrict__ Xv, int nv,
                const float* __restrict__ Xs, int ns,
                const float* __restrict__ vWl, const float* __restrict__ vatt,
                const float* __restrict__ sWl, const float* __restrict__ satt,
                int Bs, int Bv)
{
  extern __shared__ char smem_raw[];
  GatSmem& s = *reinterpret_cast<GatSmem*>(smem_raw);
  const int tid = threadIdx.x;
  const int warp = tid >> 5;
  const int bid = blockIdx.x;

  const float* X; const float* Wl; const float* attw;
  int nrows, stride, pidx, slot;
  if (bid < Bs) { slot = 1; pidx = bid;      stride = Bs; X = Xs; nrows = ns; Wl = sWl; attw = satt; }
  else          { slot = 0; pidx = bid - Bs; stride = Bv; X = Xv; nrows = nv; Wl = vWl; attw = vatt; }
  const int nsub = (nrows + 63) >> 6;

  // load full Wl -> bf16 smem
  {
    const float4* W4 = reinterpret_cast<const float4*>(Wl);
#pragma unroll 4
    for (int i = tid; i < 16384; i += 256) {
      float4 v = W4[i];
      int k = i >> 6, n = (i & 63) << 2;
      __nv_bfloat162* q = reinterpret_cast<__nv_bfloat162*>(&s.W[k * WLD + n]);
      q[0] = __floats2bfloat162_rn(v.x, v.y);
      q[1] = __floats2bfloat162_rn(v.z, v.w);
    }
  }
  s.att[tid] = attw[tid];
  s.xrb[tid] = slot ? d_xrb_s[tid] : d_xrb_v[tid];
  s.acc[tid] = 0.f;
  if (tid < 8) { s.mrun[tid] = -INFINITY; s.srun[tid] = 0.f; }

  __nv_bfloat16* A = reinterpret_cast<__nv_bfloat16*>(s.U);
  const int wr0 = (warp >> 2) << 5;   // 0 / 32
  const int wc0 = (warp & 3) << 6;    // 0 / 64 / 128 / 192

  // prefetch registers: 16 x uint2 (packed bf16x4 each)
  uint2 pf[16];
  int sub = pidx;
  if (sub < nsub) {
    const float4* X4 = reinterpret_cast<const float4*>(X) + (size_t)sub * 4096;
#pragma unroll
    for (int j = 0; j < 16; j++) {
      float4 v = X4[tid + j * 256];
      __nv_bfloat162 lo = __floats2bfloat162_rn(v.x, v.y);
      __nv_bfloat162 hi = __floats2bfloat162_rn(v.z, v.w);
      pf[j].x = *reinterpret_cast<unsigned*>(&lo);
      pf[j].y = *reinterpret_cast<unsigned*>(&hi);
    }
  }

  for (; sub < nsub; sub += stride) {
    const int row0 = sub << 6;
    __syncthreads();  // W ready (1st iter) / previous epilogue done reading U

    // ---- store prefetched A tile (bf16) ----
#pragma unroll
    for (int j = 0; j < 16; j++) {
      int i = tid + j * 256;
      int r = i >> 6, k4 = i & 63;
      *reinterpret_cast<uint2*>(&A[r * ALD + (k4 << 2)]) = pf[j];
    }
    __syncthreads();

    // ---- prefetch next tile into registers (overlaps mma below) ----
    {
      int nxt = sub + stride;
      if (nxt < nsub) {
        const float4* X4 = reinterpret_cast<const float4*>(X) + (size_t)nxt * 4096;
#pragma unroll
        for (int j = 0; j < 16; j++) {
          float4 v = X4[tid + j * 256];
          __nv_bfloat162 lo = __floats2bfloat162_rn(v.x, v.y);
          __nv_bfloat162 hi = __floats2bfloat162_rn(v.z, v.w);
          pf[j].x = *reinterpret_cast<unsigned*>(&lo);
          pf[j].y = *reinterpret_cast<unsigned*>(&hi);
        }
      }
    }

    // ---- mma: each warp 32 rows x 64 cols ----
    wmma::fragment<wmma::accumulator, 16, 16, 16, float> c[2][4];
#pragma unroll
    for (int i = 0; i < 2; i++)
#pragma unroll
      for (int j = 0; j < 4; j++) wmma::fill_fragment(c[i][j], 0.f);
#pragma unroll
    for (int kt = 0; kt < 16; kt++) {
      wmma::fragment<wmma::matrix_a, 16, 16, 16, __nv_bfloat16, wmma::row_major> a0, a1;
      wmma::load_matrix_sync(a0, &A[(wr0     ) * ALD + (kt << 4)], ALD);
      wmma::load_matrix_sync(a1, &A[(wr0 + 16) * ALD + (kt << 4)], ALD);
#pragma unroll
      for (int j = 0; j < 4; j++) {
        wmma::fragment<wmma::matrix_b, 16, 16, 16, __nv_bfloat16, wmma::row_major> b;
        wmma::load_matrix_sync(b, &s.W[(kt << 4) * WLD + wc0 + (j << 4)], WLD);
        wmma::mma_sync(c[0][j], a0, b, c[0][j]);
        wmma::mma_sync(c[1][j], a1, b, c[1][j]);
      }
    }
    __syncthreads();   // all warps done reading A; overwrite U with fp32 C
#pragma unroll
    for (int i = 0; i < 2; i++)
#pragma unroll
      for (int j = 0; j < 4; j++)
        wmma::store_matrix_sync(&s.U[(wr0 + (i << 4)) * CLD + wc0 + (j << 4)],
                                c[i][j], CLD, wmma::mem_row_major);
    __syncthreads();

    // ---- logits l[r][h] = att_h . lrelu(C[r, h*32:...] + xrb) ----
#pragma unroll
    for (int half = 0; half < 2; half++) {
      int p = tid + (half << 8);
      int h = p >> 6, r = p & 63;
      const float* Crow = &s.U[r * CLD + (h << 5)];
      const float* ath = &s.att[h << 5];
      const float* xr = &s.xrb[h << 5];
      float l;
      if (row0 + r < nrows) {
        l = 0.f;
#pragma unroll
        for (int d = 0; d < 32; d++) {
          float z = Crow[d] + xr[d];
          z = (z > 0.f) ? z : 0.2f * z;
          l = fmaf(ath[d], z, l);
        }
      } else {
        l = -INFINITY;
      }
      s.wsm[r * 8 + h] = l;
    }
    __syncthreads();

    // ---- per-head running max / scale (warp 0, shfl reduce) ----
    if (warp == 0) {
      int h = tid & 7, rg = tid >> 3;
      float m = -INFINITY;
#pragma unroll
      for (int rr = 0; rr < 16; rr++)
        m = fmaxf(m, s.wsm[((rg << 4) + rr) * 8 + h]);
      m = fmaxf(m, __shfl_xor_sync(0xffffffffu, m, 8));
      m = fmaxf(m, __shfl_xor_sync(0xffffffffu, m, 16));
      if (tid < 8) {
        float mold = s.mrun[tid];
        float mn = fmaxf(mold, m);
        s.scale[tid] = __expf(mold - mn);   // 0 on first tile
        s.mrun[tid] = mn;
      }
    }
    __syncthreads();

    // ---- exp pass (wsm flat: entry p has head p&7) ----
#pragma unroll
    for (int half = 0; half < 2; half++) {
      int p = tid + (half << 8);
      s.wsm[p] = __expf(s.wsm[p] - s.mrun[p & 7]);
    }
    __syncthreads();

    // ---- acc[c] = acc[c]*scale + sum_r w[r,h] * C[r,c] ; srun update ----
    {
      int h = tid >> 5;
      float a0 = 0.f, a1 = 0.f, a2 = 0.f, a3 = 0.f;
#pragma unroll
      for (int r = 0; r < 64; r += 4) {
        a0 = fmaf(s.wsm[(r + 0) * 8 + h], s.U[(r + 0) * CLD + tid], a0);
        a1 = fmaf(s.wsm[(r + 1) * 8 + h], s.U[(r + 1) * CLD + tid], a1);
        a2 = fmaf(s.wsm[(r + 2) * 8 + h], s.U[(r + 2) * CLD + tid], a2);
        a3 = fmaf(s.wsm[(r + 3) * 8 + h], s.U[(r + 3) * CLD + tid], a3);
      }
      s.acc[tid] = s.acc[tid] * s.scale[h] + ((a0 + a1) + (a2 + a3));
    }
    if (warp == 0) {
      int h = tid & 7, rg = tid >> 3;
      float ss = 0.f;
#pragma unroll
      for (int rr = 0; rr < 16; rr++)
        ss += s.wsm[((rg << 4) + rr) * 8 + h];
      ss += __shfl_xor_sync(0xffffffffu, ss, 8);
      ss += __shfl_xor_sync(0xffffffffu, ss, 16);
      if (tid < 8) s.srun[tid] = s.srun[tid] * s.scale[tid] + ss;
    }
  }
  __syncthreads();

  if (tid < 8) {
    d_pm[slot][pidx][tid] = s.mrun[tid];
    d_ps[slot][pidx][tid] = s.srun[tid];
  }
  d_pacc[slot][pidx][tid] = s.acc[tid];
}

// ---------------------------------------------------------------------------
// Combine block partials -> v2g/s2g, residual, LN, relu. Stores d_x, d_y.
// ---------------------------------------------------------------------------
__global__ void combine_kernel(const float* __restrict__ prev,
    const float* __restrict__ v_bl, const float* __restrict__ v_bias,
    const float* __restrict__ s_bl, const float* __restrict__ s_bias,
    const float* __restrict__ pre_ln_s, const float* __restrict__ pre_ln_b,
    int Gv, int Gs)
{
  __shared__ float Mh[16], Sh[16], ef[16][152], red[16];
  int t = threadIdx.x;
  int p = t >> 5, lane = t & 31;
  int sl = p >> 3, h = p & 7;
  int G = sl ? Gs : Gv;
  float m = -INFINITY;
  for (int b = lane; b < G; b += 32) m = fmaxf(m, d_pm[sl][b][h]);
#pragma unroll
  for (int o = 16; o; o >>= 1) m = fmaxf(m, __shfl_xor_sync(0xffffffffu, m, o));
  if (lane == 0) Mh[p] = m;
  __syncthreads();
  float M = Mh[p];
  float ssum = 0.f;
  for (int b = lane; b < G; b += 32) {
    float e = __expf(d_pm[sl][b][h] - M);
    ef[p][b] = e;
    ssum += d_ps[sl][b][h] * e;
  }
#pragma unroll
  for (int o = 16; o; o >>= 1) ssum += __shfl_xor_sync(0xffffffffu, ssum, o);
  if (lane == 0) Sh[p] = ssum;
  __syncthreads();

  int sl2 = t >> 8, c = t & 255, h2 = c >> 5, pp = sl2 * 8 + h2;
  int G2 = sl2 ? Gs : Gv;
  float f0 = 0.f, f1 = 0.f, f2 = 0.f, f3 = 0.f;
  int b = 0;
  for (; b + 4 <= G2; b += 4) {
    f0 = fmaf(d_pacc[sl2][b + 0][c], ef[pp][b + 0], f0);
    f1 = fmaf(d_pacc[sl2][b + 1][c], ef[pp][b + 1], f1);
    f2 = fmaf(d_pacc[sl2][b + 2][c], ef[pp][b + 2], f2);
    f3 = fmaf(d_pacc[sl2][b + 3][c], ef[pp][b + 3], f3);
  }
  for (; b < G2; b++) f0 = fmaf(d_pacc[sl2][b][c], ef[pp][b], f0);
  float F = (f0 + f1) + (f2 + f3);
  float g = F / Sh[pp] + (sl2 ? (s_bl[c] + s_bias[c]) : (v_bl[c] + v_bias[c]));
  float xv = prev[t] + g;

  float mean = blk_reduce_sum_512(xv, red) * (1.f / 512.f);
  float dv = xv - mean;
  float var = blk_reduce_sum_512(dv * dv, red) * (1.f / 512.f);
  float rstd = rsqrtf(var + 1e-5f);
  d_x[t] = xv;
  d_y[t] = fmaxf(dv * rstd * pre_ln_s[t] + pre_ln_b[t], 0.f);
}

// ---------------------------------------------------------------------------
// MLP: out = x_skip + (y @ mlp_W + mlp_b). 8 blocks x 64 threads, coalesced.
// ---------------------------------------------------------------------------
__global__ void mlp_kernel(const float* __restrict__ mlp_W,
                           const float* __restrict__ mlp_b,
                           float* __restrict__ out)
{
  __shared__ float ys[512];
  int tid = threadIdx.x;
  for (int i = tid; i < 512; i += 64) ys[i] = d_y[i];
  __syncthreads();
  int c = blockIdx.x * 64 + tid;
  float a0 = 0.f, a1 = 0.f, a2 = 0.f, a3 = 0.f;
#pragma unroll 4
  for (int k = 0; k < 512; k += 4) {
    a0 = fmaf(ys[k + 0], mlp_W[(k + 0) * 512 + c], a0);
    a1 = fmaf(ys[k + 1], mlp_W[(k + 1) * 512 + c], a1);
    a2 = fmaf(ys[k + 2], mlp_W[(k + 2) * 512 + c], a2);
    a3 = fmaf(ys[k + 3], mlp_W[(k + 3) * 512 + c], a3);
  }
  out[c] = d_x[c] + mlp_b[c] + ((a0 + a1) + (a2 + a3));
}

// ---------------------------------------------------------------------------
extern "C" void kernel_launch(void* const* d_in, const int* in_sizes, int n_in,
                              void* d_out, int out_size) {
  const float* view     = (const float*)d_in[0];
  const float* scene    = (const float*)d_in[1];
  const float* prev     = (const float*)d_in[2];
  const float* g2v_ln_s = (const float*)d_in[3];
  const float* g2v_ln_b = (const float*)d_in[4];
  const float* g2v_W    = (const float*)d_in[5];
  const float* g2v_b    = (const float*)d_in[6];
  const float* g2s_ln_s = (const float*)d_in[7];
  const float* g2s_ln_b = (const float*)d_in[8];
  const float* g2s_W    = (const float*)d_in[9];
  const float* g2s_b    = (const float*)d_in[10];
  const float* v_Wl     = (const float*)d_in[11];
  const float* v_bl     = (const float*)d_in[12];
  const float* v_Wr     = (const float*)d_in[13];
  const float* v_br     = (const float*)d_in[14];
  const float* v_att    = (const float*)d_in[15];
  const float* v_bias   = (const float*)d_in[16];
  const float* s_Wl     = (const float*)d_in[17];
  const float* s_bl     = (const float*)d_in[18];
  const float* s_Wr     = (const float*)d_in[19];
  const float* s_br     = (const float*)d_in[20];
  const float* s_att    = (const float*)d_in[21];
  const float* s_bias   = (const float*)d_in[22];
  const float* pre_ln_s = (const float*)d_in[23];
  const float* pre_ln_b = (const float*)d_in[24];
  const float* mlp_W    = (const float*)d_in[25];
  const float* mlp_b    = (const float*)d_in[26];
  float* out = (float*)d_out;

  int smem = (int)sizeof(GatSmem);
  cudaFuncSetAttribute(gat_kernel, cudaFuncAttributeMaxDynamicSharedMemorySize, smem);

  prep_kernel<<<1, 512>>>(prev, g2v_ln_s, g2v_ln_b, g2v_W, g2v_b,
                          g2s_ln_s, g2s_ln_b, g2s_W, g2s_b,
                          v_Wr, v_br, v_bl, s_Wr, s_br, s_bl);

  int nv = in_sizes[0] / 256;
  int ns = in_sizes[1] / 256;
  int nsub_v = (nv + 63) / 64;
  int nsub_s = (ns + 63) / 64;
  int Bv = nsub_v < 3 ? nsub_v : 3;
  int Bs = nsub_s < 145 ? nsub_s : 145;

  gat_kernel<<<Bs + Bv, 256, smem>>>(view, nv, scene, ns,
                                     v_Wl, v_att, s_Wl, s_att, Bs, Bv);

  combine_kernel<<<1, 512>>>(prev, v_bl, v_bias, s_bl, s_bias,
                             pre_ln_s, pre_ln_b, Bv, Bs);

  mlp_kernel<<<8, 64>>>(mlp_W, mlp_b, out);
}